// round 16
// baseline (speedup 1.0000x reference)
#include <cuda_runtime.h>
#include <math.h>

// Problem shape (fixed by setup_inputs): X (32, 64, 25, 2, 16, 16) fp32.
#define S_N     32
#define TVM     3200
#define NE      256
#define CHUNKS  32
#define CHUNK_M 100

// ---------------- device scratch (no allocations allowed) ----------------
__device__ float g_partial[S_N * CHUNKS * NE];
__device__ float g_G[NE];          // G (atomic-accumulated; zeroed by k_finish each replay,
                                   // zero-initialized at module load for the first call)
__device__ float g_L[S_N * NE];
__device__ float g_Gs[NE];
__device__ float g_C[NE];

// =========================================================================
// K1: partial reduction of X. grid (32,32), 256 thr; 100 matrices / block.
// Reducer threads also atomically accumulate the (pre-scaled) grand mean G.
// =========================================================================
__global__ __launch_bounds__(256) void k_partial(const float* __restrict__ X) {
    __shared__ float4 red[256];
    int s = blockIdx.x, c = blockIdx.y, t = threadIdx.x;
    int j = t & 63, gsub = t >> 6;
    const float4* p = (const float4*)(X + ((size_t)s * TVM + (size_t)c * CHUNK_M) * NE)
                      + (size_t)gsub * 25 * 64 + j;
    float4 a = make_float4(0.f, 0.f, 0.f, 0.f);
#pragma unroll
    for (int m = 0; m < 25; ++m) {
        float4 v = p[(size_t)m * 64];
        a.x += v.x; a.y += v.y; a.z += v.z; a.w += v.w;
    }
    red[t] = a;
    __syncthreads();
    if (t < 64) {
        float4 b0 = red[t], b1 = red[t + 64], b2 = red[t + 128], b3 = red[t + 192];
        float4 r = make_float4((b0.x + b1.x) + (b2.x + b3.x),
                               (b0.y + b1.y) + (b2.y + b3.y),
                               (b0.z + b1.z) + (b2.z + b3.z),
                               (b0.w + b1.w) + (b2.w + b3.w));
        ((float4*)(g_partial + (s * CHUNKS + c) * NE))[t] = r;
        const float sc = 1.f / ((float)TVM * (float)S_N);
        atomicAdd(&g_G[4 * t + 0], r.x * sc);
        atomicAdd(&g_G[4 * t + 1], r.y * sc);
        atomicAdd(&g_G[4 * t + 2], r.z * sc);
        atomicAdd(&g_G[4 * t + 3], r.w * sc);
    }
}

// =========================================================================
// Block-cooperative (128-thread, 4-warp) 16x16 toolkit.
// Thread t owns elements t (row t>>4, col t&15) and t+128 (row +8).
// Iteration counts derived ONCE from initial error norms; targets 3e-6.
// =========================================================================
__device__ __forceinline__ float wsum32(float v) {
#pragma unroll
    for (int o = 16; o; o >>= 1) v += __shfl_xor_sync(0xffffffffu, v, o);
    return v;
}
__device__ __forceinline__ float bsum128(float v, int t, volatile float* red4) {
    v = wsum32(v);
    if ((t & 31) == 0) red4[t >> 5] = v;
    __syncthreads();
    float r = (red4[0] + red4[1]) + (red4[2] + red4[3]);
    __syncthreads();
    return r;
}
__device__ __forceinline__ float btrace(const float* A, int t, volatile float* red4) {
    int i0 = t >> 4, j0 = t & 15;
    float v = 0.f;
    if (i0 == j0) v += A[t];
    if (i0 + 8 == j0) v += A[t + 128];
    return bsum128(v, t, red4);
}

// C = A * B, block-wide. Safe if C aliases A or B. Ends with __syncthreads.
__device__ __forceinline__ void bmm(float* C, const float* A, const float* B, int t) {
    int i0 = t >> 4, j0 = t & 15;
    float a0 = 0.f, a1 = 0.f;
#pragma unroll
    for (int k = 0; k < 16; ++k) {
        float bk = B[k * 16 + j0];
        a0 = fmaf(A[i0 * 16 + k], bk, a0);
        a1 = fmaf(A[(i0 + 8) * 16 + k], bk, a1);
    }
    __syncthreads();
    C[t] = a0; C[t + 128] = a1;
    __syncthreads();
}

// Coupled Newton-Schulz: Y = sqrt(A), Z = invsqrt(A). 5 distinct temps.
__device__ void b_sqrtinv(const float* A, float* Y, float* Z,
                          float* T, float* Y2, float* Z2, int t, volatile float* red4) {
    int i0 = t >> 4, j0 = t & 15;
    float s = btrace(A, t, red4) * (1.f / 16.f);
    float is0 = 1.f / s;
    float v0 = A[t] * is0 - (i0 == j0 ? 1.f : 0.f);
    float v1 = A[t + 128] * is0 - (i0 + 8 == j0 ? 1.f : 0.f);
    float d2 = bsum128(v0 * v0 + v1 * v1, t, red4);
    int n;
    if (d2 >= 0.81f) {
        if (t < 16) {
            float rs = 0.f;
            for (int k = 0; k < 16; ++k) rs += fabsf(A[t * 16 + k]);
            T[t] = rs;
        }
        __syncthreads();
        float mx = T[0];
        for (int k = 1; k < 16; ++k) mx = fmaxf(mx, T[k]);
        __syncthreads();
        s = mx; is0 = 1.f / s; n = 12;
    } else {
        float cur = sqrtf(d2); n = 0;
        while (cur > 3e-6f && n < 7) { cur = 1.3f * cur * cur; ++n; }
    }
    Y[t] = A[t] * is0;            Y[t + 128] = A[t + 128] * is0;
    Z[t] = (i0 == j0) ? 1.f : 0.f; Z[t + 128] = (i0 + 8 == j0) ? 1.f : 0.f;
    __syncthreads();
    float* y = Y; float* z = Z; float* y2 = Y2; float* z2 = Z2;
    for (int it = 0; it < n; ++it) {
        bmm(T, z, y, t);
        T[t]       = 0.5f * ((i0 == j0 ? 3.f : 0.f) - T[t]);
        T[t + 128] = 0.5f * ((i0 + 8 == j0 ? 3.f : 0.f) - T[t + 128]);
        __syncthreads();
        bmm(y2, y, T, t);
        bmm(z2, T, z, t);
        float* tm = y; y = y2; y2 = tm;
        tm = z; z = z2; z2 = tm;
    }
    float fs = sqrtf(s), fi = rsqrtf(s);
    float ry0 = y[t] * fs, ry1 = y[t + 128] * fs;
    float rz0 = z[t] * fi, rz1 = z[t + 128] * fi;
    __syncthreads();
    Y[t] = ry0; Y[t + 128] = ry1; Z[t] = rz0; Z[t + 128] = rz1;
    __syncthreads();
}

// logm(B) in place. 5 distinct temps.
__device__ void b_logm(float* B, float* t1, float* t2, float* t3,
                       float* t4, float* t5, int t, volatile float* red4) {
    int i0 = t >> 4, j0 = t & 15;
    int jsq = 0; float s, d2;
    for (;;) {
        s = btrace(B, t, red4) * (1.f / 16.f);
        float is = 1.f / s;
        float v0 = B[t] * is - (i0 == j0 ? 1.f : 0.f);
        float v1 = B[t + 128] * is - (i0 + 8 == j0 ? 1.f : 0.f);
        t1[t] = v0; t1[t + 128] = v1;
        __syncthreads();
        d2 = bsum128(v0 * v0 + v1 * v1, t, red4);
        if (d2 <= 0.25f || jsq >= 4) break;
        b_sqrtinv(B, t2, t3, t4, t5, t1, t, red4);
        float r0 = t2[t], r1 = t2[t + 128];
        __syncthreads();
        B[t] = r0; B[t + 128] = r1;
        __syncthreads();
        ++jsq;
    }
    float d = sqrtf(d2);
    int nt = 1; { float r = d; while (r > 3e-6f && nt < 24) { r *= d; ++nt; } }
    float lns = logf(s);
    float v0 = t1[t], v1 = t1[t + 128];
    B[t]       = (i0 == j0 ? lns : 0.f) + v0;
    B[t + 128] = (i0 + 8 == j0 ? lns : 0.f) + v1;
    t2[t] = v0; t2[t + 128] = v1;
    __syncthreads();
    float* P = t2; float* P2 = t3; float sg = 1.f;
    for (int k = 2; k <= nt; ++k) {
        bmm(P2, P, t1, t);
        sg = -sg; float cf = sg / (float)k;
        B[t] += cf * P2[t]; B[t + 128] += cf * P2[t + 128];
        __syncthreads();
        float* tm = P; P = P2; P2 = tm;
    }
    if (jsq) {
        float f = (float)(1 << jsq);
        B[t] *= f; B[t + 128] *= f;
        __syncthreads();
    }
}

// R = expm(A): expm(A) = e^c expm(A - cI). A preserved.
__device__ void b_expm(const float* A, float* R, float* t1, float* t2, float* t3,
                       int t, volatile float* red4) {
    int i0 = t >> 4, j0 = t & 15;
    float c0 = btrace(A, t, red4) * (1.f / 16.f);
    float v0 = A[t] - (i0 == j0 ? c0 : 0.f);
    float v1 = A[t + 128] - (i0 + 8 == j0 ? c0 : 0.f);
    t1[t] = v0; t1[t + 128] = v1;
    __syncthreads();
    float d2 = bsum128(v0 * v0 + v1 * v1, t, red4);
    int j = 0; float sc = 1.f;
    while (d2 > 0.25f && j < 20) { sc *= 0.5f; d2 *= 0.25f; ++j; }
    if (j) { t1[t] *= sc; t1[t + 128] *= sc; __syncthreads(); }
    float d = sqrtf(d2);
    int nt = 1; { float r = d; while (r > 3e-6f && nt < 14) { ++nt; r *= d / (float)nt; } }
    float ec = expf(c0 * sc);
    v0 = t1[t]; v1 = t1[t + 128];
    R[t]       = (i0 == j0 ? 1.f : 0.f) + v0;
    R[t + 128] = (i0 + 8 == j0 ? 1.f : 0.f) + v1;
    t2[t] = v0; t2[t + 128] = v1;
    __syncthreads();
    float* P = t2; float* P2 = t3;
    for (int k = 2; k <= nt; ++k) {
        bmm(P2, P, t1, t);
        float ik = 1.f / (float)k;
        float w0 = P2[t] * ik, w1 = P2[t + 128] * ik;
        P2[t] = w0; P2[t + 128] = w1;
        R[t] += w0; R[t + 128] += w1;
        __syncthreads();
        float* tm = P; P = P2; P2 = tm;
    }
    R[t] *= ec; R[t + 128] *= ec;
    __syncthreads();
    for (int q = 0; q < j; ++q) {
        bmm(t2, R, R, t);
        float r0 = t2[t], r1 = t2[t + 128];
        __syncthreads();
        R[t] = r0; R[t + 128] = r1;
        __syncthreads();
    }
}

// Dual expm with shared powers: R1 = expm(a1*S), R2 = expm(a2*S).
// Valid when max(|a1|,|a2|) * ||S - cI||_F <= 0.5 (caller guarantees via
// fallback). S preserved. Temps t1, t2, t3 distinct from S, R1, R2.
__device__ void b_expm2(const float* S, float* R1, float* R2, float a1, float a2,
                        float* t1, float* t2, float* t3, int t, volatile float* red4) {
    int i0 = t >> 4, j0 = t & 15;
    float c0 = btrace(S, t, red4) * (1.f / 16.f);
    float v0 = S[t] - (i0 == j0 ? c0 : 0.f);
    float v1 = S[t + 128] - (i0 + 8 == j0 ? c0 : 0.f);
    t1[t] = v0; t1[t + 128] = v1;
    __syncthreads();
    float d2 = bsum128(v0 * v0 + v1 * v1, t, red4);
    float amax = fmaxf(fabsf(a1), fabsf(a2));
    float d = sqrtf(d2) * amax;
    int nt = 1; { float r = d; while (r > 3e-6f && nt < 14) { ++nt; r *= d / (float)nt; } }
    float e1 = expf(c0 * a1), e2 = expf(c0 * a2);
    float f1 = a1, f2 = a2;
    v0 = t1[t]; v1 = t1[t + 128];
    R1[t]       = (i0 == j0 ? 1.f : 0.f) + f1 * v0;
    R1[t + 128] = (i0 + 8 == j0 ? 1.f : 0.f) + f1 * v1;
    R2[t]       = (i0 == j0 ? 1.f : 0.f) + f2 * v0;
    R2[t + 128] = (i0 + 8 == j0 ? 1.f : 0.f) + f2 * v1;
    t2[t] = v0; t2[t + 128] = v1;
    __syncthreads();
    float* P = t2; float* P2 = t3;
    for (int k = 2; k <= nt; ++k) {
        bmm(P2, P, t1, t);
        f1 *= a1 / (float)k; f2 *= a2 / (float)k;
        float w0 = P2[t], w1 = P2[t + 128];
        R1[t] += f1 * w0; R1[t + 128] += f1 * w1;
        R2[t] += f2 * w0; R2[t + 128] += f2 * w1;
        __syncthreads();
        float* tm = P; P = P2; P2 = tm;
    }
    R1[t] *= e1; R1[t + 128] *= e1;
    R2[t] *= e2; R2[t + 128] *= e2;
    __syncthreads();
}

// =========================================================================
// K2 (logm + fused prep + fused samplemean): 32 blocks x 128 thr.
// Each block: xmean_b from g_partial; (Gs,Gi) from g_G (redundant, parallel);
// L_b = logm(Gi xmean_b Gi). Block 0 publishes g_Gs.
// =========================================================================
__global__ __launch_bounds__(128) void k_logm() {
    __shared__ __align__(16) float m[7][256];
    __shared__ float red4[4];
    int b = blockIdx.x, t = threadIdx.x;
    {
        float a0 = 0.f, a1 = 0.f;
#pragma unroll 8
        for (int c = 0; c < CHUNKS; ++c) {
            a0 += g_partial[(b * CHUNKS + c) * NE + t];
            a1 += g_partial[(b * CHUNKS + c) * NE + t + 128];
        }
        m[6][t] = a0 * (1.f / (float)TVM);        // xmean_b
        m[6][t + 128] = a1 * (1.f / (float)TVM);
    }
    m[0][t] = g_G[t];
    m[0][t + 128] = g_G[t + 128];
    __syncthreads();
    b_sqrtinv(m[0], m[1], m[2], m[3], m[4], m[5], t, red4);   // Gs=m1, Gi=m2
    if (b == 0) { g_Gs[t] = m[1][t]; g_Gs[t + 128] = m[1][t + 128]; }
    bmm(m[3], m[2], m[6], t);          // Gi * Xm
    bmm(m[4], m[3], m[2], t);          // (Gi Xm) Gi
    b_logm(m[4], m[0], m[1], m[3], m[5], m[6], t, red4);
    g_L[b * NE + t] = m[4][t];
    g_L[b * NE + t + 128] = m[4][t + 128];
}

// =========================================================================
// K3: finish, 128 threads. Zeroes g_G for the next replay (safe: runs after
// k_logm; zero-init covers the first call).
//  Lbar -> E=expm(Lbar) -> mean = Gs E Gs.
//  Fast path (rm == I): S = logm(mean); dual expm: C=expm(-S/2),
//    geodesic=expm(0.1 S) with shared powers (guarded by norm check).
//  General fallback: sqrtinv(rm), sqrtinv(mean), full geodesic.
// =========================================================================
__global__ __launch_bounds__(128) void k_finish(const float* __restrict__ rm,
                                                float* __restrict__ out_tail, int write_tail) {
    __shared__ __align__(16) float mm[8][256];
    __shared__ float red4[4];
    int t = threadIdx.x, i0 = t >> 4, j0 = t & 15;
    g_G[t] = 0.f; g_G[t + 128] = 0.f;   // reset for next replay
    {
        float a0 = 0.f, a1 = 0.f;
#pragma unroll 8
        for (int b = 0; b < S_N; ++b) {
            a0 += g_L[b * NE + t];
            a1 += g_L[b * NE + t + 128];
        }
        mm[0][t] = a0 * (1.f / (float)S_N);
        mm[0][t + 128] = a1 * (1.f / (float)S_N);
    }
    float r0 = rm[t] - (i0 == j0 ? 1.f : 0.f);
    float r1 = rm[t + 128] - (i0 + 8 == j0 ? 1.f : 0.f);
    __syncthreads();
    float d2rm = bsum128(r0 * r0 + r1 * r1, t, red4);

    b_expm(mm[0], mm[1], mm[2], mm[3], mm[4], t, red4);   // E = mm1
    mm[2][t] = g_Gs[t]; mm[2][t + 128] = g_Gs[t + 128];
    __syncthreads();
    bmm(mm[3], mm[2], mm[1], t);
    bmm(mm[0], mm[3], mm[2], t);                          // mean = mm0

    if (d2rm < 1e-9f) {
        // fast path: rm == I
        mm[1][t] = mm[0][t]; mm[1][t + 128] = mm[0][t + 128];
        __syncthreads();
        b_logm(mm[1], mm[2], mm[3], mm[4], mm[5], mm[6], t, red4);   // S = mm1
        // ||S - cI|| check for dual-expm validity (amax = 0.5)
        float c0 = btrace(mm[1], t, red4) * (1.f / 16.f);
        float s0 = mm[1][t] - (i0 == j0 ? c0 : 0.f);
        float s1 = mm[1][t + 128] - (i0 + 8 == j0 ? c0 : 0.f);
        float d2s = bsum128(s0 * s0 + s1 * s1, t, red4);
        if (d2s * 0.25f <= 0.25f) {
            b_expm2(mm[1], mm[2], mm[3], -0.5f, 0.1f, mm[4], mm[5], mm[6], t, red4);
            g_C[t] = mm[2][t]; g_C[t + 128] = mm[2][t + 128];
            if (write_tail) { out_tail[t] = mm[3][t]; out_tail[t + 128] = mm[3][t + 128]; }
        } else {
            mm[2][t] = -0.5f * mm[1][t]; mm[2][t + 128] = -0.5f * mm[1][t + 128];
            __syncthreads();
            b_expm(mm[2], mm[3], mm[4], mm[5], mm[6], t, red4);
            g_C[t] = mm[3][t]; g_C[t + 128] = mm[3][t + 128];
            mm[2][t] = 0.1f * mm[1][t]; mm[2][t + 128] = 0.1f * mm[1][t + 128];
            __syncthreads();
            b_expm(mm[2], mm[3], mm[4], mm[5], mm[6], t, red4);
            if (write_tail) { out_tail[t] = mm[3][t]; out_tail[t + 128] = mm[3][t + 128]; }
        }
    } else {
        // general path
        mm[1][t] = rm[t]; mm[1][t + 128] = rm[t + 128];
        __syncthreads();
        b_sqrtinv(mm[1], mm[2], mm[3], mm[4], mm[5], mm[6], t, red4); // As=mm2, Ai=mm3
        b_sqrtinv(mm[0], mm[4], mm[5], mm[1], mm[6], mm[7], t, red4); // C = mm5
        g_C[t] = mm[5][t]; g_C[t + 128] = mm[5][t + 128];
        bmm(mm[4], mm[3], mm[0], t);
        bmm(mm[1], mm[4], mm[3], t);                                  // M = mm1
        b_logm(mm[1], mm[4], mm[5], mm[6], mm[7], mm[0], t, red4);
        mm[1][t] *= 0.1f; mm[1][t + 128] *= 0.1f;
        __syncthreads();
        b_expm(mm[1], mm[4], mm[5], mm[6], mm[7], t, red4);           // R = mm4
        bmm(mm[5], mm[2], mm[4], t);
        bmm(mm[6], mm[5], mm[2], t);
        if (write_tail) { out_tail[t] = mm[6][t]; out_tail[t + 128] = mm[6][t + 128]; }
    }
}

// =========================================================================
// K4 (transform v7): Y = C*X*C. 1 row/thread, 16 matrices/block.
// Aliased smem buffer (X tile then Y staging); coalesced global I/O.
// =========================================================================
typedef unsigned long long u64;
__device__ __forceinline__ u64 pk2(float lo, float hi) {
    u64 r; asm("mov.b64 %0, {%1, %2};" : "=l"(r) : "f"(lo), "f"(hi)); return r;
}
__device__ __forceinline__ void upk2(u64 v, float& lo, float& hi) {
    asm("mov.b64 {%0, %1}, %2;" : "=f"(lo), "=f"(hi) : "l"(v));
}
__device__ __forceinline__ u64 ffma2(u64 a, u64 b, u64 c) {
    u64 d; asm("fma.rn.f32x2 %0, %1, %2, %3;" : "=l"(d) : "l"(a), "l"(b), "l"(c)); return d;
}

#define MPB   16
#define XS4   66
#define YST   20
#define YMS   (16*YST)
#define SBUF  (MPB * YMS)

__global__ __launch_bounds__(256) void k_transform(const float* __restrict__ X,
                                                   float* __restrict__ Y) {
    __shared__ float4 Buf4[SBUF / 4];
    __shared__ float  Cs[256];
    float* Buf = (float*)Buf4;
    int t = threadIdx.x;
    Cs[t] = g_C[t];

    const float4* xg = (const float4*)(X + (size_t)blockIdx.x * (MPB * NE));
#pragma unroll
    for (int j = 0; j < 4; ++j) {
        int g = t + 256 * j;
        Buf4[(g >> 6) * XS4 + (g & 63)] = xg[g];
    }
    __syncthreads();

    int m = t >> 4, i = t & 15;
    const float4* xm = Buf4 + m * XS4;

    u64 w[8];
#pragma unroll
    for (int q = 0; q < 8; ++q) w[q] = pk2(0.f, 0.f);
#pragma unroll
    for (int k = 0; k < 16; ++k) {
        float ck = Cs[k * 16 + i];
        float4 a = xm[k * 4], b = xm[k * 4 + 1], c = xm[k * 4 + 2], d = xm[k * 4 + 3];
        u64 s = pk2(ck, ck);
        w[0] = ffma2(s, pk2(a.x, a.y), w[0]);
        w[1] = ffma2(s, pk2(a.z, a.w), w[1]);
        w[2] = ffma2(s, pk2(b.x, b.y), w[2]);
        w[3] = ffma2(s, pk2(b.z, b.w), w[3]);
        w[4] = ffma2(s, pk2(c.x, c.y), w[4]);
        w[5] = ffma2(s, pk2(c.z, c.w), w[5]);
        w[6] = ffma2(s, pk2(d.x, d.y), w[6]);
        w[7] = ffma2(s, pk2(d.z, d.w), w[7]);
    }
    float wf[16];
#pragma unroll
    for (int q = 0; q < 8; ++q) upk2(w[q], wf[2 * q], wf[2 * q + 1]);

    u64 y[8];
#pragma unroll
    for (int q = 0; q < 8; ++q) y[q] = pk2(0.f, 0.f);
#pragma unroll
    for (int k = 0; k < 16; ++k) {
        const float4* cp = (const float4*)(Cs + k * 16);
        float4 a = cp[0], b = cp[1], c = cp[2], d = cp[3];
        u64 s = pk2(wf[k], wf[k]);
        y[0] = ffma2(s, pk2(a.x, a.y), y[0]);
        y[1] = ffma2(s, pk2(a.z, a.w), y[1]);
        y[2] = ffma2(s, pk2(b.x, b.y), y[2]);
        y[3] = ffma2(s, pk2(b.z, b.w), y[3]);
        y[4] = ffma2(s, pk2(c.x, c.y), y[4]);
        y[5] = ffma2(s, pk2(c.z, c.w), y[5]);
        y[6] = ffma2(s, pk2(d.x, d.y), y[6]);
        y[7] = ffma2(s, pk2(d.z, d.w), y[7]);
    }

    __syncthreads();
    {
        float* yr = Buf + m * YMS + i * YST;
#pragma unroll
        for (int q = 0; q < 4; ++q) {
            float4 v;
            upk2(y[2 * q], v.x, v.y);
            upk2(y[2 * q + 1], v.z, v.w);
            *(float4*)(yr + 4 * q) = v;
        }
    }
    __syncthreads();
    float4* yg = (float4*)(Y + (size_t)blockIdx.x * (MPB * NE));
#pragma unroll
    for (int j = 0; j < 4; ++j) {
        int g = t + 256 * j;
        int mm = g >> 6, f = g & 63;
        int row = f >> 2, q = f & 3;
        yg[g] = *(const float4*)(Buf + mm * YMS + row * YST + 4 * q);
    }
}

// =========================================================================
extern "C" void kernel_launch(void* const* d_in, const int* in_sizes, int n_in,
                              void* d_out, int out_size) {
    const float* X = (const float*)d_in[0];
    const float* rm = (const float*)d_in[1];
    float* out = (float*)d_out;
    long long n_x = in_sizes[0];           // 26,214,400
    int nmat = (int)(n_x >> 8);            // 102,400
    int write_tail = ((long long)out_size - n_x) >= NE ? 1 : 0;

    k_partial<<<dim3(S_N, CHUNKS), 256>>>(X);
    k_logm<<<S_N, 128>>>();
    k_finish<<<1, 128>>>(rm, out + n_x, write_tail);
    k_transform<<<nmat / MPB, 256>>>(X, out);
}

// round 17
// speedup vs baseline: 1.3063x; 1.3063x over previous
#include <cuda_runtime.h>
#include <math.h>

// Problem shape (fixed by setup_inputs): X (32, 64, 25, 2, 16, 16) fp32.
#define S_N     32
#define TVM     3200
#define NE      256
#define CHUNKS  32
#define CHUNK_M 100

// ---------------- device scratch (no allocations allowed) ----------------
__device__ float g_partial[S_N * CHUNKS * NE];
__device__ float g_xmean[S_N * NE];
__device__ float g_G[NE];          // G (atomic-accumulated by k_samplemean; zeroed by k_partial)
__device__ float g_L[S_N * NE];
__device__ float g_Gs[NE];
__device__ float g_C[NE];

// =========================================================================
// K1: partial reduction of X. grid (32,32), 256 thr; 100 matrices / block.
// Block (0,0) also zeroes g_G for this replay (stream-ordered before K2).
// =========================================================================
__global__ __launch_bounds__(256) void k_partial(const float* __restrict__ X) {
    __shared__ float4 red[256];
    int s = blockIdx.x, c = blockIdx.y, t = threadIdx.x;
    if (s == 0 && c == 0) g_G[t] = 0.f;
    int j = t & 63, gsub = t >> 6;
    const float4* p = (const float4*)(X + ((size_t)s * TVM + (size_t)c * CHUNK_M) * NE)
                      + (size_t)gsub * 25 * 64 + j;
    float4 a = make_float4(0.f, 0.f, 0.f, 0.f);
#pragma unroll
    for (int m = 0; m < 25; ++m) {
        float4 v = p[(size_t)m * 64];
        a.x += v.x; a.y += v.y; a.z += v.z; a.w += v.w;
    }
    red[t] = a;
    __syncthreads();
    if (t < 64) {
        float4 b0 = red[t], b1 = red[t + 64], b2 = red[t + 128], b3 = red[t + 192];
        float4 r = make_float4((b0.x + b1.x) + (b2.x + b3.x),
                               (b0.y + b1.y) + (b2.y + b3.y),
                               (b0.z + b1.z) + (b2.z + b3.z),
                               (b0.w + b1.w) + (b2.w + b3.w));
        ((float4*)(g_partial + (s * CHUNKS + c) * NE))[t] = r;
    }
}

// =========================================================================
// K2: per-sample means + atomic accumulation of G. grid 32, 256 thr.
// (Low contention: 32 updates per g_G address. Do NOT move into k_partial.)
// =========================================================================
__global__ __launch_bounds__(256) void k_samplemean() {
    int b = blockIdx.x, t = threadIdx.x;
    float acc = 0.f;
#pragma unroll 8
    for (int c = 0; c < CHUNKS; ++c) acc += g_partial[(b * CHUNKS + c) * NE + t];
    acc *= (1.f / (float)TVM);
    g_xmean[b * NE + t] = acc;
    atomicAdd(&g_G[t], acc * (1.f / (float)S_N));
}

// =========================================================================
// Block-cooperative (128-thread, 4-warp) 16x16 toolkit.
// Thread t owns elements t (row t>>4, col t&15) and t+128 (row +8).
// Iteration counts derived ONCE from initial error norms; targets 3e-6.
// =========================================================================
__device__ __forceinline__ float wsum32(float v) {
#pragma unroll
    for (int o = 16; o; o >>= 1) v += __shfl_xor_sync(0xffffffffu, v, o);
    return v;
}
__device__ __forceinline__ float bsum128(float v, int t, volatile float* red4) {
    v = wsum32(v);
    if ((t & 31) == 0) red4[t >> 5] = v;
    __syncthreads();
    float r = (red4[0] + red4[1]) + (red4[2] + red4[3]);
    __syncthreads();
    return r;
}
__device__ __forceinline__ float btrace(const float* A, int t, volatile float* red4) {
    int i0 = t >> 4, j0 = t & 15;
    float v = 0.f;
    if (i0 == j0) v += A[t];
    if (i0 + 8 == j0) v += A[t + 128];
    return bsum128(v, t, red4);
}

// C = A * B, block-wide. Safe if C aliases A or B. Ends with __syncthreads.
__device__ __forceinline__ void bmm(float* C, const float* A, const float* B, int t) {
    int i0 = t >> 4, j0 = t & 15;
    float a0 = 0.f, a1 = 0.f;
#pragma unroll
    for (int k = 0; k < 16; ++k) {
        float bk = B[k * 16 + j0];
        a0 = fmaf(A[i0 * 16 + k], bk, a0);
        a1 = fmaf(A[(i0 + 8) * 16 + k], bk, a1);
    }
    __syncthreads();
    C[t] = a0; C[t + 128] = a1;
    __syncthreads();
}

// Coupled Newton-Schulz: Y = sqrt(A), Z = invsqrt(A). 5 distinct temps.
__device__ void b_sqrtinv(const float* A, float* Y, float* Z,
                          float* T, float* Y2, float* Z2, int t, volatile float* red4) {
    int i0 = t >> 4, j0 = t & 15;
    float s = btrace(A, t, red4) * (1.f / 16.f);
    float is0 = 1.f / s;
    float v0 = A[t] * is0 - (i0 == j0 ? 1.f : 0.f);
    float v1 = A[t + 128] * is0 - (i0 + 8 == j0 ? 1.f : 0.f);
    float d2 = bsum128(v0 * v0 + v1 * v1, t, red4);
    int n;
    if (d2 >= 0.81f) {          // Gershgorin fallback (unused on this data)
        if (t < 16) {
            float rs = 0.f;
            for (int k = 0; k < 16; ++k) rs += fabsf(A[t * 16 + k]);
            T[t] = rs;
        }
        __syncthreads();
        float mx = T[0];
        for (int k = 1; k < 16; ++k) mx = fmaxf(mx, T[k]);
        __syncthreads();
        s = mx; is0 = 1.f / s; n = 12;
    } else {
        float cur = sqrtf(d2); n = 0;
        while (cur > 3e-6f && n < 7) { cur = 1.3f * cur * cur; ++n; }
    }
    Y[t] = A[t] * is0;            Y[t + 128] = A[t + 128] * is0;
    Z[t] = (i0 == j0) ? 1.f : 0.f; Z[t + 128] = (i0 + 8 == j0) ? 1.f : 0.f;
    __syncthreads();
    float* y = Y; float* z = Z; float* y2 = Y2; float* z2 = Z2;
    for (int it = 0; it < n; ++it) {
        bmm(T, z, y, t);
        T[t]       = 0.5f * ((i0 == j0 ? 3.f : 0.f) - T[t]);
        T[t + 128] = 0.5f * ((i0 + 8 == j0 ? 3.f : 0.f) - T[t + 128]);
        __syncthreads();
        bmm(y2, y, T, t);
        bmm(z2, T, z, t);
        float* tm = y; y = y2; y2 = tm;
        tm = z; z = z2; z2 = tm;
    }
    float fs = sqrtf(s), fi = rsqrtf(s);
    float ry0 = y[t] * fs, ry1 = y[t + 128] * fs;
    float rz0 = z[t] * fi, rz1 = z[t + 128] * fi;
    __syncthreads();
    Y[t] = ry0; Y[t + 128] = ry1; Z[t] = rz0; Z[t + 128] = rz1;
    __syncthreads();
}

// logm(B) in place. 5 distinct temps.
__device__ void b_logm(float* B, float* t1, float* t2, float* t3,
                       float* t4, float* t5, int t, volatile float* red4) {
    int i0 = t >> 4, j0 = t & 15;
    int jsq = 0; float s, d2;
    for (;;) {
        s = btrace(B, t, red4) * (1.f / 16.f);
        float is = 1.f / s;
        float v0 = B[t] * is - (i0 == j0 ? 1.f : 0.f);
        float v1 = B[t + 128] * is - (i0 + 8 == j0 ? 1.f : 0.f);
        t1[t] = v0; t1[t + 128] = v1;
        __syncthreads();
        d2 = bsum128(v0 * v0 + v1 * v1, t, red4);
        if (d2 <= 0.25f || jsq >= 4) break;
        b_sqrtinv(B, t2, t3, t4, t5, t1, t, red4);
        float r0 = t2[t], r1 = t2[t + 128];
        __syncthreads();
        B[t] = r0; B[t + 128] = r1;
        __syncthreads();
        ++jsq;
    }
    float d = sqrtf(d2);
    int nt = 1; { float r = d; while (r > 3e-6f && nt < 24) { r *= d; ++nt; } }
    float lns = logf(s);
    float v0 = t1[t], v1 = t1[t + 128];
    B[t]       = (i0 == j0 ? lns : 0.f) + v0;
    B[t + 128] = (i0 + 8 == j0 ? lns : 0.f) + v1;
    t2[t] = v0; t2[t + 128] = v1;
    __syncthreads();
    float* P = t2; float* P2 = t3; float sg = 1.f;
    for (int k = 2; k <= nt; ++k) {
        bmm(P2, P, t1, t);
        sg = -sg; float cf = sg / (float)k;
        B[t] += cf * P2[t]; B[t + 128] += cf * P2[t + 128];
        __syncthreads();
        float* tm = P; P = P2; P2 = tm;
    }
    if (jsq) {
        float f = (float)(1 << jsq);
        B[t] *= f; B[t + 128] *= f;
        __syncthreads();
    }
}

// R = expm(A): expm(A) = e^c expm(A - cI), c = tr/16. A preserved.
__device__ void b_expm(const float* A, float* R, float* t1, float* t2, float* t3,
                       int t, volatile float* red4) {
    int i0 = t >> 4, j0 = t & 15;
    float c0 = btrace(A, t, red4) * (1.f / 16.f);
    float v0 = A[t] - (i0 == j0 ? c0 : 0.f);
    float v1 = A[t + 128] - (i0 + 8 == j0 ? c0 : 0.f);
    t1[t] = v0; t1[t + 128] = v1;
    __syncthreads();
    float d2 = bsum128(v0 * v0 + v1 * v1, t, red4);
    int j = 0; float sc = 1.f;
    while (d2 > 0.25f && j < 20) { sc *= 0.5f; d2 *= 0.25f; ++j; }
    if (j) { t1[t] *= sc; t1[t + 128] *= sc; __syncthreads(); }
    float d = sqrtf(d2);
    int nt = 1; { float r = d; while (r > 3e-6f && nt < 14) { ++nt; r *= d / (float)nt; } }
    float ec = expf(c0 * sc);
    v0 = t1[t]; v1 = t1[t + 128];
    R[t]       = (i0 == j0 ? 1.f : 0.f) + v0;
    R[t + 128] = (i0 + 8 == j0 ? 1.f : 0.f) + v1;
    t2[t] = v0; t2[t + 128] = v1;
    __syncthreads();
    float* P = t2; float* P2 = t3;
    for (int k = 2; k <= nt; ++k) {
        bmm(P2, P, t1, t);
        float ik = 1.f / (float)k;
        float w0 = P2[t] * ik, w1 = P2[t + 128] * ik;
        P2[t] = w0; P2[t + 128] = w1;
        R[t] += w0; R[t + 128] += w1;
        __syncthreads();
        float* tm = P; P = P2; P2 = tm;
    }
    R[t] *= ec; R[t + 128] *= ec;
    __syncthreads();
    for (int q = 0; q < j; ++q) {
        bmm(t2, R, R, t);
        float r0 = t2[t], r1 = t2[t + 128];
        __syncthreads();
        R[t] = r0; R[t + 128] = r1;
        __syncthreads();
    }
}

// Dual expm with shared powers: R1 = expm(a1*S), R2 = expm(a2*S).
// Valid when max(|a1|,|a2|) * ||S - cI||_F <= 0.5 (caller checks).
// S preserved. Temps t1, t2, t3 distinct from S, R1, R2.
__device__ void b_expm2(const float* S, float* R1, float* R2, float a1, float a2,
                        float* t1, float* t2, float* t3, int t, volatile float* red4) {
    int i0 = t >> 4, j0 = t & 15;
    float c0 = btrace(S, t, red4) * (1.f / 16.f);
    float v0 = S[t] - (i0 == j0 ? c0 : 0.f);
    float v1 = S[t + 128] - (i0 + 8 == j0 ? c0 : 0.f);
    t1[t] = v0; t1[t + 128] = v1;
    __syncthreads();
    float d2 = bsum128(v0 * v0 + v1 * v1, t, red4);
    float amax = fmaxf(fabsf(a1), fabsf(a2));
    float d = sqrtf(d2) * amax;
    int nt = 1; { float r = d; while (r > 3e-6f && nt < 14) { ++nt; r *= d / (float)nt; } }
    float e1 = expf(c0 * a1), e2 = expf(c0 * a2);
    float f1 = a1, f2 = a2;
    v0 = t1[t]; v1 = t1[t + 128];
    R1[t]       = (i0 == j0 ? 1.f : 0.f) + f1 * v0;
    R1[t + 128] = (i0 + 8 == j0 ? 1.f : 0.f) + f1 * v1;
    R2[t]       = (i0 == j0 ? 1.f : 0.f) + f2 * v0;
    R2[t + 128] = (i0 + 8 == j0 ? 1.f : 0.f) + f2 * v1;
    t2[t] = v0; t2[t + 128] = v1;
    __syncthreads();
    float* P = t2; float* P2 = t3;
    for (int k = 2; k <= nt; ++k) {
        bmm(P2, P, t1, t);
        f1 *= a1 / (float)k; f2 *= a2 / (float)k;
        float w0 = P2[t], w1 = P2[t + 128];
        R1[t] += f1 * w0; R1[t + 128] += f1 * w1;
        R2[t] += f2 * w0; R2[t + 128] += f2 * w1;
        __syncthreads();
        float* tm = P; P = P2; P2 = tm;
    }
    R1[t] *= e1; R1[t + 128] *= e1;
    R2[t] *= e2; R2[t + 128] *= e2;
    __syncthreads();
}

// =========================================================================
// K3 (logm + fused prep): 32 blocks x 128 thr. Each block computes (Gs,Gi)
// from g_G redundantly (parallel across SMs), then L_b = logm(Gi xmean Gi).
// Block 0 publishes g_Gs for k_finish.
// =========================================================================
__global__ __launch_bounds__(128) void k_logm() {
    __shared__ __align__(16) float m[7][256];
    __shared__ float red4[4];
    int b = blockIdx.x, t = threadIdx.x;
    m[0][t] = g_G[t];
    m[0][t + 128] = g_G[t + 128];
    __syncthreads();
    b_sqrtinv(m[0], m[1], m[2], m[3], m[4], m[5], t, red4);   // Gs=m1, Gi=m2
    if (b == 0) { g_Gs[t] = m[1][t]; g_Gs[t + 128] = m[1][t + 128]; }
    m[0][t] = g_xmean[b * NE + t];
    m[0][t + 128] = g_xmean[b * NE + t + 128];
    __syncthreads();
    bmm(m[3], m[2], m[0], t);          // Gi * Xm
    bmm(m[4], m[3], m[2], t);          // (Gi Xm) Gi
    b_logm(m[4], m[0], m[1], m[3], m[5], m[6], t, red4);
    g_L[b * NE + t] = m[4][t];
    g_L[b * NE + t + 128] = m[4][t + 128];
}

// =========================================================================
// K4: finish, 128 threads, fully block-cooperative.
//  Lbar -> E=expm(Lbar) -> mean = Gs E Gs.
//  Fast path (rm == I): S = logm(mean); dual expm with shared powers:
//    C = expm(-S/2) -> g_C, geodesic = expm(0.1 S) -> out tail (norm-guarded).
//  General fallback: sqrtinv(rm), sqrtinv(mean), full geodesic.
// =========================================================================
__global__ __launch_bounds__(128) void k_finish(const float* __restrict__ rm,
                                                float* __restrict__ out_tail, int write_tail) {
    __shared__ __align__(16) float mm[8][256];
    __shared__ float red4[4];
    int t = threadIdx.x, i0 = t >> 4, j0 = t & 15;
    {
        float a0 = 0.f, a1 = 0.f;
#pragma unroll 8
        for (int b = 0; b < S_N; ++b) {
            a0 += g_L[b * NE + t];
            a1 += g_L[b * NE + t + 128];
        }
        mm[0][t] = a0 * (1.f / (float)S_N);
        mm[0][t + 128] = a1 * (1.f / (float)S_N);
    }
    float r0 = rm[t] - (i0 == j0 ? 1.f : 0.f);
    float r1 = rm[t + 128] - (i0 + 8 == j0 ? 1.f : 0.f);
    __syncthreads();
    float d2rm = bsum128(r0 * r0 + r1 * r1, t, red4);

    b_expm(mm[0], mm[1], mm[2], mm[3], mm[4], t, red4);   // E = mm1
    mm[2][t] = g_Gs[t]; mm[2][t + 128] = g_Gs[t + 128];
    __syncthreads();
    bmm(mm[3], mm[2], mm[1], t);
    bmm(mm[0], mm[3], mm[2], t);                          // mean = mm0

    if (d2rm < 1e-9f) {
        // fast path: rm == I  =>  As = Ai = I
        mm[1][t] = mm[0][t]; mm[1][t + 128] = mm[0][t + 128];
        __syncthreads();
        b_logm(mm[1], mm[2], mm[3], mm[4], mm[5], mm[6], t, red4);   // S = mm1
        float c0 = btrace(mm[1], t, red4) * (1.f / 16.f);
        float s0 = mm[1][t] - (i0 == j0 ? c0 : 0.f);
        float s1 = mm[1][t + 128] - (i0 + 8 == j0 ? c0 : 0.f);
        float d2s = bsum128(s0 * s0 + s1 * s1, t, red4);
        if (d2s * 0.25f <= 0.25f) {
            // dual expm, powers shared between the two series
            b_expm2(mm[1], mm[2], mm[3], -0.5f, 0.1f, mm[4], mm[5], mm[6], t, red4);
            g_C[t] = mm[2][t]; g_C[t + 128] = mm[2][t + 128];
            if (write_tail) { out_tail[t] = mm[3][t]; out_tail[t + 128] = mm[3][t + 128]; }
        } else {
            mm[2][t] = -0.5f * mm[1][t]; mm[2][t + 128] = -0.5f * mm[1][t + 128];
            __syncthreads();
            b_expm(mm[2], mm[3], mm[4], mm[5], mm[6], t, red4);
            g_C[t] = mm[3][t]; g_C[t + 128] = mm[3][t + 128];
            mm[2][t] = 0.1f * mm[1][t]; mm[2][t + 128] = 0.1f * mm[1][t + 128];
            __syncthreads();
            b_expm(mm[2], mm[3], mm[4], mm[5], mm[6], t, red4);
            if (write_tail) { out_tail[t] = mm[3][t]; out_tail[t + 128] = mm[3][t + 128]; }
        }
    } else {
        // general path
        mm[1][t] = rm[t]; mm[1][t + 128] = rm[t + 128];
        __syncthreads();
        b_sqrtinv(mm[1], mm[2], mm[3], mm[4], mm[5], mm[6], t, red4); // As=mm2, Ai=mm3
        b_sqrtinv(mm[0], mm[4], mm[5], mm[1], mm[6], mm[7], t, red4); // C = mm5
        g_C[t] = mm[5][t]; g_C[t + 128] = mm[5][t + 128];
        bmm(mm[4], mm[3], mm[0], t);
        bmm(mm[1], mm[4], mm[3], t);                                  // M = mm1
        b_logm(mm[1], mm[4], mm[5], mm[6], mm[7], mm[0], t, red4);
        mm[1][t] *= 0.1f; mm[1][t + 128] *= 0.1f;
        __syncthreads();
        b_expm(mm[1], mm[4], mm[5], mm[6], mm[7], t, red4);           // R = mm4
        bmm(mm[5], mm[2], mm[4], t);
        bmm(mm[6], mm[5], mm[2], t);
        if (write_tail) { out_tail[t] = mm[6][t]; out_tail[t + 128] = mm[6][t + 128]; }
    }
}

// =========================================================================
// K5 (transform v7): Y = C*X*C. 1 row/thread, 16 matrices/block.
// Aliased smem buffer (X tile then Y staging); coalesced global I/O.
// =========================================================================
typedef unsigned long long u64;
__device__ __forceinline__ u64 pk2(float lo, float hi) {
    u64 r; asm("mov.b64 %0, {%1, %2};" : "=l"(r) : "f"(lo), "f"(hi)); return r;
}
__device__ __forceinline__ void upk2(u64 v, float& lo, float& hi) {
    asm("mov.b64 {%0, %1}, %2;" : "=f"(lo), "=f"(hi) : "l"(v));
}
__device__ __forceinline__ u64 ffma2(u64 a, u64 b, u64 c) {
    u64 d; asm("fma.rn.f32x2 %0, %1, %2, %3;" : "=l"(d) : "l"(a), "l"(b), "l"(c)); return d;
}

#define MPB   16
#define XS4   66
#define YST   20
#define YMS   (16*YST)
#define SBUF  (MPB * YMS)

__global__ __launch_bounds__(256) void k_transform(const float* __restrict__ X,
                                                   float* __restrict__ Y) {
    __shared__ float4 Buf4[SBUF / 4];
    __shared__ float  Cs[256];
    float* Buf = (float*)Buf4;
    int t = threadIdx.x;
    Cs[t] = g_C[t];

    const float4* xg = (const float4*)(X + (size_t)blockIdx.x * (MPB * NE));
#pragma unroll
    for (int j = 0; j < 4; ++j) {
        int g = t + 256 * j;
        Buf4[(g >> 6) * XS4 + (g & 63)] = xg[g];
    }
    __syncthreads();

    int m = t >> 4, i = t & 15;
    const float4* xm = Buf4 + m * XS4;

    u64 w[8];
#pragma unroll
    for (int q = 0; q < 8; ++q) w[q] = pk2(0.f, 0.f);
#pragma unroll
    for (int k = 0; k < 16; ++k) {
        float ck = Cs[k * 16 + i];
        float4 a = xm[k * 4], b = xm[k * 4 + 1], c = xm[k * 4 + 2], d = xm[k * 4 + 3];
        u64 s = pk2(ck, ck);
        w[0] = ffma2(s, pk2(a.x, a.y), w[0]);
        w[1] = ffma2(s, pk2(a.z, a.w), w[1]);
        w[2] = ffma2(s, pk2(b.x, b.y), w[2]);
        w[3] = ffma2(s, pk2(b.z, b.w), w[3]);
        w[4] = ffma2(s, pk2(c.x, c.y), w[4]);
        w[5] = ffma2(s, pk2(c.z, c.w), w[5]);
        w[6] = ffma2(s, pk2(d.x, d.y), w[6]);
        w[7] = ffma2(s, pk2(d.z, d.w), w[7]);
    }
    float wf[16];
#pragma unroll
    for (int q = 0; q < 8; ++q) upk2(w[q], wf[2 * q], wf[2 * q + 1]);

    u64 y[8];
#pragma unroll
    for (int q = 0; q < 8; ++q) y[q] = pk2(0.f, 0.f);
#pragma unroll
    for (int k = 0; k < 16; ++k) {
        const float4* cp = (const float4*)(Cs + k * 16);
        float4 a = cp[0], b = cp[1], c = cp[2], d = cp[3];
        u64 s = pk2(wf[k], wf[k]);
        y[0] = ffma2(s, pk2(a.x, a.y), y[0]);
        y[1] = ffma2(s, pk2(a.z, a.w), y[1]);
        y[2] = ffma2(s, pk2(b.x, b.y), y[2]);
        y[3] = ffma2(s, pk2(b.z, b.w), y[3]);
        y[4] = ffma2(s, pk2(c.x, c.y), y[4]);
        y[5] = ffma2(s, pk2(c.z, c.w), y[5]);
        y[6] = ffma2(s, pk2(d.x, d.y), y[6]);
        y[7] = ffma2(s, pk2(d.z, d.w), y[7]);
    }

    __syncthreads();
    {
        float* yr = Buf + m * YMS + i * YST;
#pragma unroll
        for (int q = 0; q < 4; ++q) {
            float4 v;
            upk2(y[2 * q], v.x, v.y);
            upk2(y[2 * q + 1], v.z, v.w);
            *(float4*)(yr + 4 * q) = v;
        }
    }
    __syncthreads();
    float4* yg = (float4*)(Y + (size_t)blockIdx.x * (MPB * NE));
#pragma unroll
    for (int j = 0; j < 4; ++j) {
        int g = t + 256 * j;
        int mm = g >> 6, f = g & 63;
        int row = f >> 2, q = f & 3;
        yg[g] = *(const float4*)(Buf + mm * YMS + row * YST + 4 * q);
    }
}

// =========================================================================
extern "C" void kernel_launch(void* const* d_in, const int* in_sizes, int n_in,
                              void* d_out, int out_size) {
    const float* X = (const float*)d_in[0];
    const float* rm = (const float*)d_in[1];
    float* out = (float*)d_out;
    long long n_x = in_sizes[0];           // 26,214,400
    int nmat = (int)(n_x >> 8);            // 102,400
    int write_tail = ((long long)out_size - n_x) >= NE ? 1 : 0;

    k_partial<<<dim3(S_N, CHUNKS), 256>>>(X);
    k_samplemean<<<S_N, 256>>>();
    k_logm<<<S_N, 128>>>();
    k_finish<<<1, 128>>>(rm, out + n_x, write_tail);
    k_transform<<<nmat / MPB, 256>>>(X, out);
}